// round 14
// baseline (speedup 1.0000x reference)
#include <cuda_runtime.h>
#include <math.h>

// ---------------------------------------------------------------------------
// Butterfly module, round 14. SINGLE kernel launch.
//
// R13 compute path (packed f32x2, LDS.128 rot constants, frsqrt activation)
// with the LOAD side rebuilt as a bulk-async staging pipeline:
//   - CTA prologue issues 2 slices x 16 rows of cp.async.bulk (2KB each,
//     64KB total) into double-buffered dynamic smem, completion via mbarrier
//     expect_tx. The whole CTA read-set is in flight immediately.
//   - Compute reads staged rows via conflict-free LDS.64 (29cyc) instead of
//     16 outstanding LDG.64 (577cyc) -> long-scoreboard stalls collapse into
//     one mbarrier wait per slice.
//   - Stores remain direct streaming STG.64 (fire-and-forget).
// ---------------------------------------------------------------------------

typedef unsigned long long u64;

#define CURV2_PK  0x3C23D70A3C23D70AULL   // (0.01f, 0.01f)
#define HALF_PK   0x3F0000003F000000ULL   // (0.5f, 0.5f)

#define SLICE_BYTES   2048                // 512 floats per row-slice
#define SLICE_FLOATS  512
#define TILE_BYTES    (16 * SLICE_BYTES)  // 32KB per slice buffer

__device__ __forceinline__ u64 pack2(float x, float y) {
    u64 r; asm("mov.b64 %0, {%1, %2};" : "=l"(r) : "f"(x), "f"(y)); return r;
}
__device__ __forceinline__ float2 unpack2(u64 v) {
    float2 r; asm("mov.b64 {%0, %1}, %2;" : "=f"(r.x), "=f"(r.y) : "l"(v)); return r;
}
__device__ __forceinline__ u64 fma2(u64 a, u64 b, u64 c) {
    u64 d; asm("fma.rn.f32x2 %0, %1, %2, %3;" : "=l"(d) : "l"(a), "l"(b), "l"(c));
    return d;
}
__device__ __forceinline__ u64 mul2(u64 a, u64 b) {
    u64 d; asm("mul.rn.f32x2 %0, %1, %2;" : "=l"(d) : "l"(a), "l"(b)); return d;
}
__device__ __forceinline__ u64 add2(u64 a, u64 b) {
    u64 d; asm("add.rn.f32x2 %0, %1, %2;" : "=l"(d) : "l"(a), "l"(b)); return d;
}
__device__ __forceinline__ u64 sub2(u64 a, u64 b) {
    u64 d; asm("sub.rn.f32x2 %0, %1, %2;" : "=l"(d) : "l"(a), "l"(b)); return d;
}

__device__ __forceinline__ unsigned smem_u32(const void* p) {
    return (unsigned)__cvta_generic_to_shared(p);
}
__device__ __forceinline__ void mbar_init(unsigned mbar, unsigned cnt) {
    asm volatile("mbarrier.init.shared.b64 [%0], %1;" :: "r"(mbar), "r"(cnt)
                 : "memory");
}
__device__ __forceinline__ void mbar_expect_tx(unsigned mbar, unsigned bytes) {
    asm volatile("mbarrier.arrive.expect_tx.shared.b64 _, [%0], %1;"
                 :: "r"(mbar), "r"(bytes) : "memory");
}
__device__ __forceinline__ void bulk_g2s(unsigned dst, const void* src,
                                         unsigned bytes, unsigned mbar) {
    asm volatile(
        "cp.async.bulk.shared::cta.global.mbarrier::complete_tx::bytes "
        "[%0], [%1], %2, [%3];"
        :: "r"(dst), "l"(src), "r"(bytes), "r"(mbar) : "memory");
}
__device__ __forceinline__ void mbar_wait(unsigned mbar, unsigned parity) {
    asm volatile(
        "{\n\t"
        ".reg .pred p;\n\t"
        "WAIT_%=:\n\t"
        "mbarrier.try_wait.parity.acquire.cta.shared::cta.b64 p, [%0], %1, 0x989680;\n\t"
        "@!p bra WAIT_%=;\n\t"
        "}"
        :: "r"(mbar), "r"(parity) : "memory");
}

// One butterfly layer (stride S) on 16 packed-f32x2 rows.
// srot: 8 {c2,s2} pairs (16B each) ordered by ascending low-row offset.
template <int S>
__device__ __forceinline__ void blayer16(u64 a[16],
                                         const ulonglong2* __restrict__ srot) {
    int p = 0;
#pragma unroll
    for (int o = 0; o < 16; ++o) {
        if ((o & S) == 0) {
            ulonglong2 r = srot[p++];          // LDS.128: {c2, s2}
            u64 l = a[o], h = a[o + S];
            a[o]     = fma2(r.x, l, mul2(r.y, h));
            a[o + S] = sub2(mul2(r.x, h), mul2(r.y, l));
        }
    }
}

__global__ __launch_bounds__(256)
void butterfly_fused_kernel(const float* __restrict__ data,
                            const float* __restrict__ angles,
                            const float* __restrict__ biases,
                            const int*   __restrict__ idx_in,
                            const int*   __restrict__ idx_out,
                            float*       __restrict__ out,
                            int N, int B, int NB, int R)
{
    const int tid = threadIdx.x;
    const int by  = blockIdx.y;

    // ---------------- tail blocks: pass-through copy of uncovered rows ------
    if (by >= NB) {
        if (blockIdx.x != 0) return;          // one block per 16-row group
        __shared__ unsigned int covmask;
        const int base = (by - NB) * 16;
        if (tid == 0) covmask = 0;
        __syncthreads();
        for (int i = tid; i < N; i += 256) {
            int r = idx_out[i] - base;
            if ((unsigned)r < 16u) atomicOr(&covmask, 1u << r);
        }
        __syncthreads();
        unsigned int cm = covmask;
#pragma unroll 1
        for (int r = 0; r < 16; ++r) {
            int row = base + r;
            if (row >= R || (cm >> r) & 1u) continue;
            const float4* src = reinterpret_cast<const float4*>(data + (size_t)row * B);
            float4*       dst = reinterpret_cast<float4*>(out + (size_t)row * B);
            for (int i = tid; i < (B >> 2); i += blockDim.x)
                dst[i] = src[i];
        }
        return;
    }

    // ---------------- butterfly blocks --------------------------------------
    extern __shared__ __align__(128) unsigned char dynsmem[];
    float* buf[2] = { reinterpret_cast<float*>(dynsmem),
                      reinterpret_cast<float*>(dynsmem + TILE_BYTES) };

    __shared__ ulonglong2 srot[64];   // [layer 0..7][pair 0..7] = {c2, s2}
    __shared__ u64 sb2[8];            // packed biases
    __shared__ int oin[16], oout[16]; // premultiplied row offsets (elements)
    __shared__ alignas(8) u64 mbars[2];

    const int blk = by;

    if (tid < 64) {
        int l = tid >> 3, p = tid & 7;
        float ang = angles[(size_t)l * (N >> 1) + blk * 8 + p];
        float s, c;
        __sincosf(ang, &s, &c);
        srot[tid].x = pack2(c, c);
        srot[tid].y = pack2(s, s);
    }
    if (tid < 8) {
        float b = biases[blk * 8 + tid];
        sb2[tid] = pack2(b, b);
    }
    if (tid < 16) {
        oin[tid]  = idx_in [blk * 16 + tid] * B;
        oout[tid] = idx_out[blk * 16 + tid] * B;
    }
    if (tid == 0) {
        mbar_init(smem_u32(&mbars[0]), 1);
        mbar_init(smem_u32(&mbars[1]), 1);
    }
    __syncthreads();

    const int colbase = blockIdx.x * 1024;

    // ---- issue the CTA's ENTIRE read set as bulk async copies -------------
    if (tid == 0) {
#pragma unroll 1
        for (int s = 0; s < 2; ++s) {
            unsigned mb = smem_u32(&mbars[s]);
            mbar_expect_tx(mb, TILE_BYTES);
            unsigned dst = smem_u32(buf[s]);
            const int col = colbase + s * SLICE_FLOATS;
#pragma unroll
            for (int i = 0; i < 16; ++i)
                bulk_g2s(dst + i * SLICE_BYTES,
                         data + (size_t)(oin[i] + col),
                         SLICE_BYTES, mb);
        }
    }

#pragma unroll 1
    for (int sub = 0; sub < 2; ++sub) {
        mbar_wait(smem_u32(&mbars[sub]), 0);

        const float* bp = buf[sub];
        const int col = colbase + sub * SLICE_FLOATS;

        // --- read 16 staged rows (conflict-free LDS.64) ---
        u64 a[16];
#pragma unroll
        for (int i = 0; i < 16; ++i)
            a[i] = *reinterpret_cast<const u64*>(bp + i * SLICE_FLOATS + tid * 2);

        // --- input layers: strides 1,2,4,8 ---
        blayer16<1>(a, srot + 0);
        blayer16<2>(a, srot + 8);
        blayer16<4>(a, srot + 16);
        blayer16<8>(a, srot + 24);

        // --- fused bias + smooth relu on rows 0-7 ---
#pragma unroll
        for (int i = 0; i < 8; ++i) {
            u64 xa = add2(a[i], sb2[i]);
            u64 t  = fma2(xa, xa, CURV2_PK);          // xa^2 + curv^2  (>= 0.01)
            float2 tf = unpack2(t);
            float s0 = __frsqrt_rn(tf.x) * tf.x;      // sqrt(t) via MUFU
            float s1 = __frsqrt_rn(tf.y) * tf.y;
            a[i] = mul2(HALF_PK, add2(xa, pack2(s0, s1)));
        }

        // --- output layers: strides 1,2,4,8 ---
        blayer16<1>(a, srot + 32);
        blayer16<2>(a, srot + 40);
        blayer16<4>(a, srot + 48);
        blayer16<8>(a, srot + 56);

        // --- store (streaming, direct to gmem) ---
#pragma unroll
        for (int i = 0; i < 16; ++i)
            __stcs(reinterpret_cast<u64*>(out + (size_t)(oout[i] + col * 1) + tid * 2),
                   a[i]);
    }
}

extern "C" void kernel_launch(void* const* d_in, const int* in_sizes, int n_in,
                              void* d_out, int out_size)
{
    const float* data    = (const float*)d_in[0];
    const float* angles  = (const float*)d_in[1];
    const float* biases  = (const float*)d_in[2];
    const int*   idx_in  = (const int*)d_in[3];
    const int*   idx_out = (const int*)d_in[4];
    float*       out     = (float*)d_out;

    const int N  = in_sizes[3];            // gathered rows (4096)
    const int B  = in_sizes[0] / N;        // row width (8192)
    const int R  = out_size / B;           // rows in out
    const int NB = N / 16;                 // butterfly row-blocks
    const int CG = (R + 15) / 16;          // copy row-groups

    const int dyn_smem = 2 * TILE_BYTES;   // 64KB double buffer

    static bool attr_set = false;          // first call is uncaptured
    if (!attr_set) {
        cudaFuncSetAttribute(butterfly_fused_kernel,
                             cudaFuncAttributeMaxDynamicSharedMemorySize,
                             dyn_smem);
        attr_set = true;
    }

    // single launch:
    //   y in [0, NB)     : butterfly, CTA = 16 rows x 1024 cols (2 slices)
    //   y in [NB, NB+CG) : pass-through copy (x==0 only; scans idx_out)
    dim3 grid(B / 1024, NB + CG);
    butterfly_fused_kernel<<<grid, 256, dyn_smem>>>(data, angles, biases,
                                                    idx_in, idx_out, out,
                                                    N, B, NB, R);
}

// round 15
// speedup vs baseline: 1.0463x; 1.0463x over previous
#include <cuda_runtime.h>
#include <math.h>

// ---------------------------------------------------------------------------
// Butterfly module, round 15. SINGLE kernel launch.
//
// R13 (best, 49.9us) + two latency-exposure fixes:
//  1) Slice 2 staged via per-thread cp.async.cg (LDGSTS) into 32KB smem,
//     issued BEFORE slice-1 compute -> slice-2 DRAM latency fully hidden.
//     (256 issuing threads; no mbarrier; 4 CTAs/SM preserved.)
//  2) Slice-1 layers s1,s2,s4 computed on rows 0-7 first (depends only on
//     the first 8 loads), then rows 8-15 -> overlaps the tail loads.
// ---------------------------------------------------------------------------

typedef unsigned long long u64;

#define CURV2_PK  0x3C23D70A3C23D70AULL   // (0.01f, 0.01f)
#define HALF_PK   0x3F0000003F000000ULL   // (0.5f, 0.5f)

#define SLICE_FLOATS  512
#define SLICE_BYTES   2048                // bytes per row-slice
#define TILE_BYTES    (16 * SLICE_BYTES)  // 32KB stage buffer

__device__ __forceinline__ u64 pack2(float x, float y) {
    u64 r; asm("mov.b64 %0, {%1, %2};" : "=l"(r) : "f"(x), "f"(y)); return r;
}
__device__ __forceinline__ float2 unpack2(u64 v) {
    float2 r; asm("mov.b64 {%0, %1}, %2;" : "=f"(r.x), "=f"(r.y) : "l"(v)); return r;
}
__device__ __forceinline__ u64 fma2(u64 a, u64 b, u64 c) {
    u64 d; asm("fma.rn.f32x2 %0, %1, %2, %3;" : "=l"(d) : "l"(a), "l"(b), "l"(c));
    return d;
}
__device__ __forceinline__ u64 mul2(u64 a, u64 b) {
    u64 d; asm("mul.rn.f32x2 %0, %1, %2;" : "=l"(d) : "l"(a), "l"(b)); return d;
}
__device__ __forceinline__ u64 add2(u64 a, u64 b) {
    u64 d; asm("add.rn.f32x2 %0, %1, %2;" : "=l"(d) : "l"(a), "l"(b)); return d;
}
__device__ __forceinline__ u64 sub2(u64 a, u64 b) {
    u64 d; asm("sub.rn.f32x2 %0, %1, %2;" : "=l"(d) : "l"(a), "l"(b)); return d;
}

__device__ __forceinline__ unsigned smem_u32(const void* p) {
    return (unsigned)__cvta_generic_to_shared(p);
}
__device__ __forceinline__ void cp_async16(unsigned dst, const void* src) {
    asm volatile("cp.async.cg.shared.global [%0], [%1], 16;"
                 :: "r"(dst), "l"(src) : "memory");
}
__device__ __forceinline__ void cp_async_commit() {
    asm volatile("cp.async.commit_group;" ::: "memory");
}
__device__ __forceinline__ void cp_async_wait_all() {
    asm volatile("cp.async.wait_group 0;" ::: "memory");
}

// Full 16-row butterfly layer, stride S; srot = 8 {c2,s2} pairs (asc. low).
template <int S>
__device__ __forceinline__ void blayer16(u64 a[16],
                                         const ulonglong2* __restrict__ srot) {
    int p = 0;
#pragma unroll
    for (int o = 0; o < 16; ++o) {
        if ((o & S) == 0) {
            ulonglong2 r = srot[p++];          // LDS.128: {c2, s2}
            u64 l = a[o], h = a[o + S];
            a[o]     = fma2(r.x, l, mul2(r.y, h));
            a[o + S] = sub2(mul2(r.x, h), mul2(r.y, l));
        }
    }
}

// Half layer: stride S in {1,2,4} on rows [base, base+8).
// Global pair rank = 4*(base/8) + local rank  -> pass srot already offset.
template <int S>
__device__ __forceinline__ void blayer8(u64* a8,
                                        const ulonglong2* __restrict__ srot) {
    int p = 0;
#pragma unroll
    for (int o = 0; o < 8; ++o) {
        if ((o & S) == 0) {
            ulonglong2 r = srot[p++];
            u64 l = a8[o], h = a8[o + S];
            a8[o]     = fma2(r.x, l, mul2(r.y, h));
            a8[o + S] = sub2(mul2(r.x, h), mul2(r.y, l));
        }
    }
}

__global__ __launch_bounds__(256)
void butterfly_fused_kernel(const float* __restrict__ data,
                            const float* __restrict__ angles,
                            const float* __restrict__ biases,
                            const int*   __restrict__ idx_in,
                            const int*   __restrict__ idx_out,
                            float*       __restrict__ out,
                            int N, int B, int NB, int R)
{
    const int tid = threadIdx.x;
    const int by  = blockIdx.y;

    // ---------------- tail blocks: pass-through copy of uncovered rows ------
    if (by >= NB) {
        if (blockIdx.x != 0) return;          // one block per 16-row group
        __shared__ unsigned int covmask;
        const int base = (by - NB) * 16;
        if (tid == 0) covmask = 0;
        __syncthreads();
        for (int i = tid; i < N; i += 256) {
            int r = idx_out[i] - base;
            if ((unsigned)r < 16u) atomicOr(&covmask, 1u << r);
        }
        __syncthreads();
        unsigned int cm = covmask;
#pragma unroll 1
        for (int r = 0; r < 16; ++r) {
            int row = base + r;
            if (row >= R || (cm >> r) & 1u) continue;
            const float4* src = reinterpret_cast<const float4*>(data + (size_t)row * B);
            float4*       dst = reinterpret_cast<float4*>(out + (size_t)row * B);
            for (int i = tid; i < (B >> 2); i += blockDim.x)
                dst[i] = src[i];
        }
        return;
    }

    // ---------------- butterfly blocks --------------------------------------
    extern __shared__ __align__(128) unsigned char stage[];   // 32KB slice-2 buf

    __shared__ ulonglong2 srot[64];   // [layer 0..7][pair 0..7] = {c2, s2}
    __shared__ u64 sb2[8];            // packed biases
    __shared__ int oin[16], oout[16]; // premultiplied row offsets (elements)

    const int blk = by;

    if (tid < 64) {
        int l = tid >> 3, p = tid & 7;
        float ang = angles[(size_t)l * (N >> 1) + blk * 8 + p];
        float s, c;
        __sincosf(ang, &s, &c);
        srot[tid].x = pack2(c, c);
        srot[tid].y = pack2(s, s);
    }
    if (tid < 8) {
        float b = biases[blk * 8 + tid];
        sb2[tid] = pack2(b, b);
    }
    if (tid < 16) {
        oin[tid]  = idx_in [blk * 16 + tid] * B;
        oout[tid] = idx_out[blk * 16 + tid] * B;
    }
    __syncthreads();

    const int colbase = blockIdx.x * 1024;
    const int col1 = colbase + tid * 2;                 // slice-1 column
    const int col2base = colbase + SLICE_FLOATS;        // slice-2 origin

    // --- slice 1: direct loads into registers (16-deep MLP) ---
    u64 a[16];
#pragma unroll
    for (int i = 0; i < 16; ++i)
        a[i] = __ldcs(reinterpret_cast<const u64*>(data + (size_t)(oin[i] + col1)));

    // --- slice 2: stage via cp.async while slice 1 computes ---
    {
        unsigned sbase = smem_u32(stage);
#pragma unroll
        for (int k = 0; k < 8; ++k) {
            int chunk = tid + k * 256;            // 2048 x 16B chunks
            int row   = chunk >> 7;               // 128 chunks per row
            int off   = (chunk & 127) * 4;        // floats within the row slice
            cp_async16(sbase + chunk * 16,
                       data + (size_t)(oin[row] + col2base + off));
        }
        cp_async_commit();
    }

    // --- slice-1 input layers: halves first (overlap tail loads) ---
    blayer8<1>(a,     srot + 0);      // rows 0-7, ranks 0-3
    blayer8<2>(a,     srot + 8);
    blayer8<4>(a,     srot + 16);
    blayer8<1>(a + 8, srot + 4);      // rows 8-15, ranks 4-7
    blayer8<2>(a + 8, srot + 12);
    blayer8<4>(a + 8, srot + 20);
    blayer16<8>(a,    srot + 24);     // stride-8 couples the halves

    // --- fused bias + smooth relu on rows 0-7 ---
#pragma unroll
    for (int i = 0; i < 8; ++i) {
        u64 xa = add2(a[i], sb2[i]);
        u64 t  = fma2(xa, xa, CURV2_PK);
        float2 tf = unpack2(t);
        float s0 = __frsqrt_rn(tf.x) * tf.x;
        float s1 = __frsqrt_rn(tf.y) * tf.y;
        a[i] = mul2(HALF_PK, add2(xa, pack2(s0, s1)));
    }

    // --- slice-1 output layers ---
    blayer16<1>(a, srot + 32);
    blayer16<2>(a, srot + 40);
    blayer16<4>(a, srot + 48);
    blayer16<8>(a, srot + 56);

    // --- store slice 1 (streaming) ---
#pragma unroll
    for (int i = 0; i < 16; ++i)
        __stcs(reinterpret_cast<u64*>(out + (size_t)(oout[i] + col1)), a[i]);

    // ================= slice 2 (from smem stage) ===========================
    cp_async_wait_all();
    __syncthreads();

    const float* bp = reinterpret_cast<const float*>(stage);
#pragma unroll
    for (int i = 0; i < 16; ++i)
        a[i] = *reinterpret_cast<const u64*>(bp + i * SLICE_FLOATS + tid * 2);

    blayer16<1>(a, srot + 0);
    blayer16<2>(a, srot + 8);
    blayer16<4>(a, srot + 16);
    blayer16<8>(a, srot + 24);

#pragma unroll
    for (int i = 0; i < 8; ++i) {
        u64 xa = add2(a[i], sb2[i]);
        u64 t  = fma2(xa, xa, CURV2_PK);
        float2 tf = unpack2(t);
        float s0 = __frsqrt_rn(tf.x) * tf.x;
        float s1 = __frsqrt_rn(tf.y) * tf.y;
        a[i] = mul2(HALF_PK, add2(xa, pack2(s0, s1)));
    }

    blayer16<1>(a, srot + 32);
    blayer16<2>(a, srot + 40);
    blayer16<4>(a, srot + 48);
    blayer16<8>(a, srot + 56);

    const int col2 = col2base + tid * 2;
#pragma unroll
    for (int i = 0; i < 16; ++i)
        __stcs(reinterpret_cast<u64*>(out + (size_t)(oout[i] + col2)), a[i]);
}

extern "C" void kernel_launch(void* const* d_in, const int* in_sizes, int n_in,
                              void* d_out, int out_size)
{
    const float* data    = (const float*)d_in[0];
    const float* angles  = (const float*)d_in[1];
    const float* biases  = (const float*)d_in[2];
    const int*   idx_in  = (const int*)d_in[3];
    const int*   idx_out = (const int*)d_in[4];
    float*       out     = (float*)d_out;

    const int N  = in_sizes[3];            // gathered rows (4096)
    const int B  = in_sizes[0] / N;        // row width (8192)
    const int R  = out_size / B;           // rows in out
    const int NB = N / 16;                 // butterfly row-blocks
    const int CG = (R + 15) / 16;          // copy row-groups

    // single launch:
    //   y in [0, NB)     : butterfly, CTA = 16 rows x 1024 cols (2 slices)
    //   y in [NB, NB+CG) : pass-through copy (x==0 only; scans idx_out)
    dim3 grid(B / 1024, NB + CG);
    butterfly_fused_kernel<<<grid, 256, TILE_BYTES>>>(data, angles, biases,
                                                      idx_in, idx_out, out,
                                                      N, B, NB, R);
}

// round 16
// speedup vs baseline: 1.1146x; 1.0653x over previous
#include <cuda_runtime.h>
#include <math.h>

// ---------------------------------------------------------------------------
// Butterfly module, round 16. SINGLE kernel launch.
//
// R13 (best, 49.9us) with ONE reg-neutral change: per slice, loads are split
// into two 8-row batches with the first-half layers (s1,s2,s4 confined to
// rows 0-7) computed between them. An asm memory barrier stops ptxas from
// re-merging the batches. MLP_p1 16 -> 8 (less L1tex queue contention),
// and first compute starts after 8 loads instead of ~all 16 (6 SB slots).
// No staging, no extra registers, 4 CTAs/SM preserved.
// ---------------------------------------------------------------------------

typedef unsigned long long u64;

#define CURV2_PK  0x3C23D70A3C23D70AULL   // (0.01f, 0.01f)
#define HALF_PK   0x3F0000003F000000ULL   // (0.5f, 0.5f)

__device__ __forceinline__ u64 pack2(float x, float y) {
    u64 r; asm("mov.b64 %0, {%1, %2};" : "=l"(r) : "f"(x), "f"(y)); return r;
}
__device__ __forceinline__ float2 unpack2(u64 v) {
    float2 r; asm("mov.b64 {%0, %1}, %2;" : "=f"(r.x), "=f"(r.y) : "l"(v)); return r;
}
__device__ __forceinline__ u64 fma2(u64 a, u64 b, u64 c) {
    u64 d; asm("fma.rn.f32x2 %0, %1, %2, %3;" : "=l"(d) : "l"(a), "l"(b), "l"(c));
    return d;
}
__device__ __forceinline__ u64 mul2(u64 a, u64 b) {
    u64 d; asm("mul.rn.f32x2 %0, %1, %2;" : "=l"(d) : "l"(a), "l"(b)); return d;
}
__device__ __forceinline__ u64 add2(u64 a, u64 b) {
    u64 d; asm("add.rn.f32x2 %0, %1, %2;" : "=l"(d) : "l"(a), "l"(b)); return d;
}
__device__ __forceinline__ u64 sub2(u64 a, u64 b) {
    u64 d; asm("sub.rn.f32x2 %0, %1, %2;" : "=l"(d) : "l"(a), "l"(b)); return d;
}

// Full 16-row butterfly layer, stride S; srot = 8 {c2,s2} pairs (asc. low).
template <int S>
__device__ __forceinline__ void blayer16(u64 a[16],
                                         const ulonglong2* __restrict__ srot) {
    int p = 0;
#pragma unroll
    for (int o = 0; o < 16; ++o) {
        if ((o & S) == 0) {
            ulonglong2 r = srot[p++];          // LDS.128: {c2, s2}
            u64 l = a[o], h = a[o + S];
            a[o]     = fma2(r.x, l, mul2(r.y, h));
            a[o + S] = sub2(mul2(r.x, h), mul2(r.y, l));
        }
    }
}

// Half layer: stride S in {1,2,4} on 8 rows. Global rank = 4*half + local,
// so callers pass srot pre-offset by 4*half. (Validated R15: same rel_err.)
template <int S>
__device__ __forceinline__ void blayer8(u64* a8,
                                        const ulonglong2* __restrict__ srot) {
    int p = 0;
#pragma unroll
    for (int o = 0; o < 8; ++o) {
        if ((o & S) == 0) {
            ulonglong2 r = srot[p++];
            u64 l = a8[o], h = a8[o + S];
            a8[o]     = fma2(r.x, l, mul2(r.y, h));
            a8[o + S] = sub2(mul2(r.x, h), mul2(r.y, l));
        }
    }
}

__global__ __launch_bounds__(256)
void butterfly_fused_kernel(const float* __restrict__ data,
                            const float* __restrict__ angles,
                            const float* __restrict__ biases,
                            const int*   __restrict__ idx_in,
                            const int*   __restrict__ idx_out,
                            float*       __restrict__ out,
                            int N, int B, int NB, int R)
{
    const int tid = threadIdx.x;
    const int by  = blockIdx.y;

    // ---------------- tail blocks: pass-through copy of uncovered rows ------
    if (by >= NB) {
        if (blockIdx.x != 0) return;          // one block per 16-row group
        __shared__ unsigned int covmask;
        const int base = (by - NB) * 16;
        if (tid == 0) covmask = 0;
        __syncthreads();
        for (int i = tid; i < N; i += 256) {
            int r = idx_out[i] - base;
            if ((unsigned)r < 16u) atomicOr(&covmask, 1u << r);
        }
        __syncthreads();
        unsigned int cm = covmask;
#pragma unroll 1
        for (int r = 0; r < 16; ++r) {
            int row = base + r;
            if (row >= R || (cm >> r) & 1u) continue;
            const float4* src = reinterpret_cast<const float4*>(data + (size_t)row * B);
            float4*       dst = reinterpret_cast<float4*>(out + (size_t)row * B);
            for (int i = tid; i < (B >> 2); i += blockDim.x)
                dst[i] = src[i];
        }
        return;
    }

    // ---------------- butterfly blocks --------------------------------------
    __shared__ ulonglong2 srot[64];   // [layer 0..7][pair 0..7] = {c2, s2}
    __shared__ u64 sb2[8];            // packed biases
    __shared__ int oin[16], oout[16]; // premultiplied row offsets (elements)

    const int blk = by;

    if (tid < 64) {
        int l = tid >> 3, p = tid & 7;
        float ang = angles[(size_t)l * (N >> 1) + blk * 8 + p];
        float s, c;
        __sincosf(ang, &s, &c);
        srot[tid].x = pack2(c, c);
        srot[tid].y = pack2(s, s);
    }
    if (tid < 8) {
        float b = biases[blk * 8 + tid];
        sb2[tid] = pack2(b, b);
    }
    if (tid < 16) {
        oin[tid]  = idx_in [blk * 16 + tid] * B;
        oout[tid] = idx_out[blk * 16 + tid] * B;
    }
    __syncthreads();

    const int col0 = blockIdx.x * 1024 + tid * 2;

#pragma unroll 1
    for (int sub = 0; sub < 2; ++sub) {
        const int col = col0 + sub * 512;

        u64 a[16];

        // --- batch 1: rows 0-7 ---
#pragma unroll
        for (int i = 0; i < 8; ++i)
            a[i] = __ldcs(reinterpret_cast<const u64*>(data + (size_t)(oin[i] + col)));

        // keep the two load batches distinct (MLP_p1 = 8, not 16)
        asm volatile("" ::: "memory");

        // --- batch 2: rows 8-15 (in flight while first-half computes) ---
#pragma unroll
        for (int i = 8; i < 16; ++i)
            a[i] = __ldcs(reinterpret_cast<const u64*>(data + (size_t)(oin[i] + col)));

        // --- first-half input layers (depend only on rows 0-7) ---
        blayer8<1>(a, srot + 0);
        blayer8<2>(a, srot + 8);
        blayer8<4>(a, srot + 16);

        // --- second-half input layers ---
        blayer8<1>(a + 8, srot + 4);
        blayer8<2>(a + 8, srot + 12);
        blayer8<4>(a + 8, srot + 20);

        // --- stride-8 couples the halves ---
        blayer16<8>(a, srot + 24);

        // --- fused bias + smooth relu on rows 0-7 ---
#pragma unroll
        for (int i = 0; i < 8; ++i) {
            u64 xa = add2(a[i], sb2[i]);
            u64 t  = fma2(xa, xa, CURV2_PK);          // xa^2 + curv^2  (>= 0.01)
            float2 tf = unpack2(t);
            float s0 = __frsqrt_rn(tf.x) * tf.x;      // sqrt(t) via MUFU
            float s1 = __frsqrt_rn(tf.y) * tf.y;
            a[i] = mul2(HALF_PK, add2(xa, pack2(s0, s1)));
        }

        // --- output layers: strides 1,2,4,8 ---
        blayer16<1>(a, srot + 32);
        blayer16<2>(a, srot + 40);
        blayer16<4>(a, srot + 48);
        blayer16<8>(a, srot + 56);

        // --- store (streaming) ---
#pragma unroll
        for (int i = 0; i < 16; ++i)
            __stcs(reinterpret_cast<u64*>(out + (size_t)(oout[i] + col)), a[i]);
    }
}

extern "C" void kernel_launch(void* const* d_in, const int* in_sizes, int n_in,
                              void* d_out, int out_size)
{
    const float* data    = (const float*)d_in[0];
    const float* angles  = (const float*)d_in[1];
    const float* biases  = (const float*)d_in[2];
    const int*   idx_in  = (const int*)d_in[3];
    const int*   idx_out = (const int*)d_in[4];
    float*       out     = (float*)d_out;

    const int N  = in_sizes[3];            // gathered rows (4096)
    const int B  = in_sizes[0] / N;        // row width (8192)
    const int R  = out_size / B;           // rows in out
    const int NB = N / 16;                 // butterfly row-blocks
    const int CG = (R + 15) / 16;          // copy row-groups

    // single launch:
    //   y in [0, NB)     : butterfly, CTA = 16 rows x 1024 cols (2 slices)
    //   y in [NB, NB+CG) : pass-through copy (x==0 only; scans idx_out)
    dim3 grid(B / 1024, NB + CG);
    butterfly_fused_kernel<<<grid, 256>>>(data, angles, biases, idx_in,
                                          idx_out, out, N, B, NB, R);
}